// round 15
// baseline (speedup 1.0000x reference)
#include <cuda_runtime.h>
#include <cstdint>
#include <math.h>

#define NB 32
#define TVn 3200
#define BN_INV 0.9999950000374997f

// ---------------- scratch ----------------
__device__ float g_wp  [327680];
__device__ float g_xT  [(size_t)NB*TVn*128];
__device__ float g_qkT [(size_t)NB*TVn*192];
__device__ float g_atts[(size_t)NB*3*128*704];
__device__ float g_yT  [(size_t)NB*TVn*384];
__device__ float g_s1T [(size_t)NB*TVn*128];
__device__ float g_soT [(size_t)NB*TVn*128];
__device__ float g_sbar[(size_t)NB*128*128];
__device__ float g_qtm [(size_t)NB*128*256];
__device__ float g_att [(size_t)NB*4*128*128];
__device__ float g_tmaj[(size_t)NB*25*128*128];
__device__ float g_zT  [(size_t)NB*TVn*512];
__device__ float g_toT [(size_t)NB*TVn*128];
__device__ float g_tnc [(size_t)NB*128*TVn];

#define OFF_WINS  0
#define OFF_WOUTS 32768
#define OFF_WFFS  81920
#define OFF_WINT  98304
#define OFF_WOUTT 131072
#define OFF_WFFT  196608
#define OFF_WTCN  212992
#define W_TOTAL   327680

// narrow kernel smem
#define RS     36
#define BOFF_F 4608
#define STG_F  9216
#define NSTAGE 3
#define SMEMSZ (STG_F * NSTAGE * 4)

// wide kernel smem: A 128 + B 256 rows, RS stride, 4 stages + mbarriers
#define BOFFW_F 4608
#define STGW_F  13824
#define NSTW    4
#define MBAR_W  (STGW_F * NSTW)              // word offset of mbarriers
#define SMEMW   (STGW_F * NSTW * 4 + 64)     // 221248 B

// ---------------- helpers ----------------
__device__ __forceinline__ uint32_t smem_u32(const void* p){
    uint32_t a;
    asm("{ .reg .u64 t; cvta.to.shared.u64 t, %1; cvt.u32.u64 %0, t; }" : "=r"(a) : "l"(p));
    return a;
}
__device__ __forceinline__ uint32_t f2tf32(float f){
    uint32_t r; asm("cvt.rna.tf32.f32 %0, %1;" : "=r"(r) : "f"(f)); return r;
}
__device__ __forceinline__ float tanh_ap(float x){
    float r; asm("tanh.approx.f32 %0, %1;" : "=f"(r) : "f"(x)); return r;
}
__device__ __forceinline__ void mma_tf32(float* d, const uint32_t* a, const uint32_t* b){
    asm volatile("mma.sync.aligned.m16n8k8.row.col.f32.tf32.tf32.f32 "
        "{%0,%1,%2,%3}, {%4,%5,%6,%7}, {%8,%9}, {%0,%1,%2,%3};"
        : "+f"(d[0]), "+f"(d[1]), "+f"(d[2]), "+f"(d[3])
        : "r"(a[0]), "r"(a[1]), "r"(a[2]), "r"(a[3]), "r"(b[0]), "r"(b[1]));
}
#define MBWAIT(bar, ph) \
    asm volatile("{\n\t.reg .pred P;\n\tW%=:\n\tmbarrier.try_wait.parity.shared::cta.b64 P, [%0], %1, 0x989680;\n\t@P bra D%=;\n\tbra W%=;\n\tD%=:\n\t}" \
                 :: "r"(bar), "r"(ph) : "memory")

// ================= narrow kernel (G3 only, cp.async path) =================
__device__ __forceinline__ void compute_chunk(uint32_t stage_b, int lane,
                                              int wm, int wn, float acc[4][4][4]){
    const int arow = (lane & 7) + ((lane >> 3) & 1) * 8;
    const uint32_t aoff = ((lane >> 4) & 1) * 16;
    const int brow = lane & 7;
    const uint32_t boff = ((lane >> 3) & 1) * 16;
    const uint32_t abase = stage_b + (uint32_t)((wm + arow) * RS) * 4u + aoff;
    const uint32_t bbase = stage_b + (uint32_t)(BOFF_F + (wn + brow) * RS) * 4u + boff;
    #pragma unroll
    for (int k8 = 0; k8 < 4; k8++){
        uint32_t af[4][4], bf[4][2];
        #pragma unroll
        for (int mt = 0; mt < 4; mt++){
            uint32_t ad = abase + (uint32_t)(mt * 16 * RS) * 4u + k8 * 32;
            asm volatile("ldmatrix.sync.aligned.m8n8.x4.shared.b16 {%0,%1,%2,%3}, [%4];"
                : "=r"(af[mt][0]), "=r"(af[mt][1]), "=r"(af[mt][2]), "=r"(af[mt][3])
                : "r"(ad));
        }
        #pragma unroll
        for (int nt = 0; nt < 4; nt++){
            uint32_t bd = bbase + (uint32_t)(nt * 8 * RS) * 4u + k8 * 32;
            asm volatile("ldmatrix.sync.aligned.m8n8.x2.shared.b16 {%0,%1}, [%2];"
                : "=r"(bf[nt][0]), "=r"(bf[nt][1])
                : "r"(bd));
        }
        #pragma unroll
        for (int mt = 0; mt < 4; mt++)
            #pragma unroll
            for (int nt = 0; nt < 4; nt++)
                mma_tf32(acc[mt][nt], af[mt], bf[nt]);
    }
}

template<bool BIAS,bool PRED>
__global__ __launch_bounds__(256,2)
void mma_gemm(const float* __restrict__ A, const float* __restrict__ Bp,
              float* __restrict__ Cp, const float* __restrict__ bias,
              int Ka, int Bld, int ldc, int Mvalid, int nch, int Np)
{
    extern __shared__ uint32_t sm[];
    const uint32_t sbw = smem_u32(sm);
    const int tid = threadIdx.x, lane = tid & 31, wid = tid >> 5;
    const int wm = (wid >> 2) * 64, wn = (wid & 3) * 32;
    const int lq = lane >> 2, klo = lane & 3;

    const int n = blockIdx.z;
    const int m0 = blockIdx.y * 128;
    const int p0 = blockIdx.x * 128;
    const float* Bb = Bp + (size_t)n * Np * Bld;

    const int r = tid & 127, kh = (tid >> 7) * 16;
    const float* parow = A + (size_t)(m0 + r) * Ka + kh;

    float acc[4][4][4];
    #pragma unroll
    for (int a = 0; a < 4; a++)
        #pragma unroll
        for (int b = 0; b < 4; b++)
            #pragma unroll
            for (int c = 0; c < 4; c++) acc[a][b][c] = 0.f;

#define ISSUE(cc, stg) {                                                         \
        const int k0_ = (cc) * 32;                                               \
        const float* asrc_ = parow + k0_;                                        \
        const float* bsrc_ = Bb + (size_t)(p0 + r) * Bld + k0_ + kh;             \
        const uint32_t ad_ = sbw + 4u * ((stg) * STG_F + r * RS + kh);           \
        const uint32_t bd_ = sbw + 4u * ((stg) * STG_F + BOFF_F + r * RS + kh);  \
        _Pragma("unroll")                                                        \
        for (int i = 0; i < 4; i++){                                             \
            asm volatile("cp.async.cg.shared.global [%0], [%1], 16;"             \
                         :: "r"(ad_ + 16u*i), "l"(asrc_ + i*4) : "memory");      \
            asm volatile("cp.async.cg.shared.global [%0], [%1], 16;"             \
                         :: "r"(bd_ + 16u*i), "l"(bsrc_ + i*4) : "memory");      \
        } }

    ISSUE(0, 0)
    asm volatile("cp.async.commit_group;" ::: "memory");
    ISSUE(1, 1)
    asm volatile("cp.async.commit_group;" ::: "memory");

    for (int c = 0; c < nch; c++) {
        asm volatile("cp.async.wait_group 1;" ::: "memory");
        __syncthreads();
        compute_chunk(sbw + 4u * ((c % NSTAGE) * STG_F), lane, wm, wn, acc);
        const int nc = c + 2;
        if (nc < nch) { ISSUE(nc, nc % NSTAGE) }
        asm volatile("cp.async.commit_group;" ::: "memory");
    }
#undef ISSUE

    asm volatile("cp.async.wait_group 0;" ::: "memory");
    __syncthreads();
    float* smf = reinterpret_cast<float*>(sm);

    #pragma unroll
    for (int mt = 0; mt < 4; mt++)
        #pragma unroll
        for (int h = 0; h < 2; h++)
            #pragma unroll
            for (int nt = 0; nt < 4; nt++)
                #pragma unroll
                for (int q = 0; q < 2; q++) {
                    const int m = wm + mt*16 + lq + h*8;
                    const int col = wn + nt*8 + klo*2 + q;
                    smf[col*132 + m] = acc[mt][nt][h*2 + q];
                }
    __syncthreads();

    #pragma unroll
    for (int it = 0; it < 16; it++) {
        const int idx = it*256 + tid;
        const int col = idx >> 5, m4 = (idx & 31) * 4;
        const int mg0 = m0 + m4;
        if (PRED && mg0 >= Mvalid) continue;
        float4 v4 = *(float4*)&smf[col*132 + m4];
        float vv[4] = {v4.x, v4.y, v4.z, v4.w};
        float4 b4;
        if (BIAS) b4 = *(const float4*)(bias + mg0);
        const float* bp = (const float*)&b4;
        float4 o4; float* op = (float*)&o4;
        #pragma unroll
        for (int j = 0; j < 4; j++) {
            float v = vv[j];
            if (BIAS) v += bp[j];
            op[j] = v;
        }
        *(float4*)(Cp + ((size_t)n*Np + p0 + col)*ldc + mg0) = o4;
    }
}

// ================= wide kernel: 128M x 256N, bulk-copy pipeline =================
__device__ __forceinline__ void compute_chunk_w(uint32_t stage_b, int lane,
                                                int wm, int wn, float acc[2][8][4]){
    const int arow = (lane & 7) + ((lane >> 3) & 1) * 8;
    const uint32_t aoff = ((lane >> 4) & 1) * 16;
    const int brow = (lane & 7) + ((lane >> 4) & 1) * 8;
    const uint32_t boff = ((lane >> 3) & 1) * 16;
    const uint32_t abase = stage_b + (uint32_t)((wm + arow) * RS) * 4u + aoff;
    const uint32_t bbase = stage_b + (uint32_t)(BOFFW_F + (wn + brow) * RS) * 4u + boff;
    #pragma unroll
    for (int k8 = 0; k8 < 4; k8++){
        uint32_t af[2][4], bf[8][2];
        #pragma unroll
        for (int mt = 0; mt < 2; mt++){
            uint32_t ad = abase + (uint32_t)(mt * 16 * RS) * 4u + k8 * 32;
            asm volatile("ldmatrix.sync.aligned.m8n8.x4.shared.b16 {%0,%1,%2,%3}, [%4];"
                : "=r"(af[mt][0]), "=r"(af[mt][1]), "=r"(af[mt][2]), "=r"(af[mt][3])
                : "r"(ad));
        }
        #pragma unroll
        for (int ng = 0; ng < 4; ng++){
            uint32_t bd = bbase + (uint32_t)(ng * 16 * RS) * 4u + k8 * 32;
            asm volatile("ldmatrix.sync.aligned.m8n8.x4.shared.b16 {%0,%1,%2,%3}, [%4];"
                : "=r"(bf[2*ng][0]), "=r"(bf[2*ng][1]), "=r"(bf[2*ng+1][0]), "=r"(bf[2*ng+1][1])
                : "r"(bd));
        }
        #pragma unroll
        for (int mt = 0; mt < 2; mt++)
            #pragma unroll
            for (int nt = 0; nt < 8; nt++)
                mma_tf32(acc[mt][nt], af[mt], bf[nt]);
    }
}

template<int ZM,int BSHIFT,int CM,bool BIAS,bool BNORM,bool RES,bool LRELU,bool PRED>
__global__ __launch_bounds__(512,1)
void mma_gemm_w(const float* __restrict__ A, const float* __restrict__ Bp,
                float* __restrict__ Cp,
                const float* __restrict__ bias, const float* __restrict__ gam,
                const float* __restrict__ bet, const float* __restrict__ resT,
                int Ka, int Bld, int ldc, int Mvalid, int nch, int Np)
{
    extern __shared__ uint32_t sm[];
    const uint32_t sbw = smem_u32(sm);
    const uint32_t mbar = sbw + 4u * MBAR_W;
    const int tid = threadIdx.x, lane = tid & 31, wid = tid >> 5;
    const int wm = (wid >> 2) * 32, wn = (wid & 3) * 64;
    const int lq = lane >> 2, klo = lane & 3;

    int n, s4 = 0;
    if (ZM == 0) { n = blockIdx.z; }
    else { n = blockIdx.z >> 2; s4 = blockIdx.z & 3; }
    const int m0 = blockIdx.y * 128;
    const int p0 = blockIdx.x * 256;
    const float* Ab = (ZM == 0) ? A : A + (size_t)blockIdx.z * 16384;
    const float* Bb = (ZM == 0) ? Bp + (size_t)n * Np * Bld
                                : Bp + (size_t)n * 25 * 16384;

    if (tid == 0) {
        #pragma unroll
        for (int s = 0; s < NSTW; s++)
            asm volatile("mbarrier.init.shared.b64 [%0], 1;" :: "r"(mbar + s*8) : "memory");
    }
    __syncthreads();

    float acc[2][8][4];
    #pragma unroll
    for (int a = 0; a < 2; a++)
        #pragma unroll
        for (int b = 0; b < 8; b++)
            #pragma unroll
            for (int c = 0; c < 4; c++) acc[a][b][c] = 0.f;

    // bulk issue: one 128B cp.async.bulk per tile row (A rows 0-127, B rows 128-383)
#define ISSUEB(cc) {                                                             \
        const int stg_ = (cc) & 3;                                               \
        const int k0_ = (cc) * 32;                                               \
        int k0B_, sh_;                                                           \
        if (BSHIFT){ int j_ = (cc) >> 2; k0B_ = ((cc) & 3) * 32; sh_ = (j_-3)*25;}\
        else { k0B_ = k0_; sh_ = 0; }                                            \
        int lo_ = -(p0 + sh_); if (lo_ < 0) lo_ = 0;                             \
        int hi_ = 256;                                                           \
        { int t2_ = Np - p0; if (t2_ < hi_) hi_ = t2_;                           \
          int t3_ = TVn - sh_ - p0; if (t3_ < hi_) hi_ = t3_; }                  \
        if (hi_ < lo_) hi_ = lo_;                                                \
        const uint32_t bar_ = mbar + stg_ * 8;                                   \
        if (tid == 0) {                                                          \
            unsigned bytes_ = (128u + (unsigned)(hi_ - lo_)) * 128u;             \
            asm volatile("mbarrier.arrive.expect_tx.shared.b64 _, [%0], %1;"     \
                         :: "r"(bar_), "r"(bytes_) : "memory");                  \
        }                                                                        \
        if (tid < 384) {                                                         \
            const uint32_t dst_ = sbw + 4u * (stg_ * STGW_F + tid * RS);         \
            if (tid < 128) {                                                     \
                const float* src_ = Ab + (size_t)(m0 + tid) * Ka + k0_;          \
                asm volatile("cp.async.bulk.shared::cluster.global.mbarrier::complete_tx::bytes [%0], [%1], 128, [%2];" \
                             :: "r"(dst_), "l"(src_), "r"(bar_) : "memory");     \
            } else {                                                             \
                const int br_ = tid - 128;                                       \
                if (br_ >= lo_ && br_ < hi_) {                                   \
                    const float* src_ = Bb + (size_t)(p0 + br_ + sh_) * Bld + k0B_; \
                    asm volatile("cp.async.bulk.shared::cluster.global.mbarrier::complete_tx::bytes [%0], [%1], 128, [%2];" \
                                 :: "r"(dst_), "l"(src_), "r"(bar_) : "memory"); \
                } else {                                                         \
                    _Pragma("unroll")                                            \
                    for (int q_ = 0; q_ < 8; q_++)                               \
                        asm volatile("st.shared.v4.b32 [%0], {%1,%1,%1,%1};"     \
                                     :: "r"(dst_ + (uint32_t)(q_*16)), "r"(0u) : "memory"); \
                }                                                                \
            }                                                                    \
        } }

    ISSUEB(0)
    ISSUEB(1)
    ISSUEB(2)
    __syncthreads();   // make prologue STS-zeros visible before first consume

    for (int c = 0; c < nch; c++) {
        MBWAIT(mbar + (c & 3) * 8, (c >> 2) & 1);
        compute_chunk_w(sbw + 4u * ((c & 3) * STGW_F), lane, wm, wn, acc);
        __syncthreads();
        const int nc = c + 3;
        if (nc < nch) { ISSUEB(nc) }
    }
#undef ISSUEB

    // ---- single-pass epilogue over all freed stages ----
    float* ep = reinterpret_cast<float*>(sm);
    #pragma unroll
    for (int mt = 0; mt < 2; mt++)
        #pragma unroll
        for (int h = 0; h < 2; h++)
            #pragma unroll
            for (int nt = 0; nt < 8; nt++)
                #pragma unroll
                for (int q = 0; q < 2; q++) {
                    const int m = wm + mt*16 + lq + h*8;
                    const int cl = wn + nt*8 + klo*2 + q;   // 0..255
                    if (CM == 0) ep[cl*132 + m] = acc[mt][nt][h*2 + q];
                    else         ep[m*260 + cl] = acc[mt][nt][h*2 + q];
                }
    __syncthreads();

    #pragma unroll
    for (int it = 0; it < 16; it++) {
        const int idx = it*512 + tid;
        if (CM == 0) {
            const int col = idx >> 5, m4 = (idx & 31) * 4;
            const int mg0 = m0 + m4;
            if (PRED && mg0 >= Mvalid) continue;
            if (p0 + col >= Np) continue;
            float4 v4 = *(float4*)&ep[col*132 + m4];
            float vv[4] = {v4.x, v4.y, v4.z, v4.w};
            float4 b4, g4, e4, r4;
            if (BIAS)  b4 = *(const float4*)(bias + mg0);
            if (BNORM){ g4 = *(const float4*)(gam + mg0); e4 = *(const float4*)(bet + mg0); }
            if (RES)   r4 = *(const float4*)(resT + ((size_t)n*Np + p0 + col)*128 + mg0);
            const float* bp = (const float*)&b4; const float* gp = (const float*)&g4;
            const float* epp = (const float*)&e4; const float* rp = (const float*)&r4;
            float4 o4; float* op = (float*)&o4;
            #pragma unroll
            for (int j = 0; j < 4; j++) {
                float v = vv[j];
                if (BIAS)  v += bp[j];
                if (BNORM) v = v * (gp[j] * BN_INV) + epp[j];
                if (RES)   v += rp[j];
                if (LRELU) v = v > 0.f ? v : 0.1f * v;
                op[j] = v;
            }
            *(float4*)(Cp + ((size_t)n*Np + p0 + col)*ldc + mg0) = o4;
        } else if (CM == 1) {
            const int m = idx >> 6, c4l = (idx & 63) * 4;
            const int mg = m0 + m;
            if (p0 + c4l >= Np) continue;
            float4 v4 = *(float4*)&ep[m*260 + c4l];
            float vv[4] = {v4.x, v4.y, v4.z, v4.w};
            float bi = BIAS ? bias[mg] : 0.f;
            float sc = BNORM ? gam[mg] * BN_INV : 1.f;
            float sh = BNORM ? bet[mg] : 0.f;
            float4 r4;
            if (RES) r4 = *(const float4*)(resT + ((size_t)(n*128 + mg))*TVn + p0 + c4l);
            const float* rp = (const float*)&r4;
            float4 o4; float* op = (float*)&o4;
            #pragma unroll
            for (int j = 0; j < 4; j++) {
                float v = vv[j] + bi;
                if (BNORM) v = v * sc + sh;
                if (RES)   v += rp[j];
                if (LRELU) v = v > 0.f ? v : 0.1f * v;
                op[j] = v;
            }
            *(float4*)(Cp + ((size_t)(n*128 + mg))*TVn + p0 + c4l) = o4;
        } else {
            // CM==3: zT[n][m*25+v][s4*128+c]
            const int m = idx >> 6, c4l = (idx & 63) * 4;
            const int gc = p0 + c4l;
            if (gc >= Np) continue;
            const int vv25 = gc >> 7, cmod = gc & 127;
            float4 v4 = *(float4*)&ep[m*260 + c4l];
            *(float4*)(Cp + ((size_t)n*TVn + (size_t)m*25 + vv25)*512 + s4*128 + cmod) = v4;
        }
    }
}

// ---------------- prep kernels ----------------
__global__ void pack_all(const float* __restrict__ w_in_s, const float* __restrict__ w_out_s,
                         const float* __restrict__ w_ff_s, const float* __restrict__ w_in_t,
                         const float* __restrict__ w_out_t, const float* __restrict__ w_ff_t,
                         const float* __restrict__ w_tcn)
{
    int idx = blockIdx.x * blockDim.x + threadIdx.x;
    if (idx >= W_TOTAL) return;
    const float* src; int off, Msrc, K, tcn = 0;
    if      (idx < OFF_WOUTS){ src = w_in_s;  off = OFF_WINS;  Msrc = 192; K = 128; }
    else if (idx < OFF_WINT) { if (idx < OFF_WFFS){ src = w_out_s; off = OFF_WOUTS; Msrc = 128; K = 384; }
                               else              { src = w_ff_s;  off = OFF_WFFS;  Msrc = 128; K = 128; } }
    else if (idx < OFF_WOUTT){ src = w_in_t;  off = OFF_WINT;  Msrc = 256; K = 128; }
    else if (idx < OFF_WFFT) { src = w_out_t; off = OFF_WOUTT; Msrc = 128; K = 512; }
    else if (idx < OFF_WTCN) { src = w_ff_t;  off = OFF_WFFT;  Msrc = 128; K = 128; }
    else                     { src = w_tcn;   off = OFF_WTCN;  Msrc = 128; K = 896; tcn = 1; }
    int local = idx - off;
    int mrow = local / K, k = local - mrow * K;
    float v = 0.f;
    if (mrow < Msrc) {
        if (tcn) { int j = k >> 7, c = k & 127; v = src[(mrow * 128 + c) * 7 + j]; }
        else     { v = src[(size_t)mrow * K + k]; }
    }
    g_wp[idx] = __uint_as_float(f2tf32(v));
}

__global__ __launch_bounds__(256) void txpose_x(const float* __restrict__ x, int nbase)
{
    __shared__ float t[32][33];
    int p0 = blockIdx.x * 32, c0 = blockIdx.y * 32, n = nbase + blockIdx.z;
    int tx = threadIdx.x & 31, ty = threadIdx.x >> 5;
    for (int r = ty; r < 32; r += 8)
        t[r][tx] = x[((size_t)n * 128 + c0 + r) * TVn + p0 + tx];
    __syncthreads();
    for (int r = ty; r < 32; r += 8)
        g_xT[(size_t)n * TVn * 128 + (size_t)(p0 + r) * 128 + c0 + tx] = t[tx][r];
}

__global__ __launch_bounds__(256) void txpose_inv()
{
    __shared__ float t[32][33];
    int p0 = blockIdx.x * 32, c0 = blockIdx.y * 32, n = blockIdx.z;
    int tx = threadIdx.x & 31, ty = threadIdx.x >> 5;
    for (int r = ty; r < 32; r += 8)
        t[r][tx] = g_toT[((size_t)n * TVn + p0 + r) * 128 + c0 + tx];
    __syncthreads();
    for (int r = ty; r < 32; r += 8)
        g_tnc[((size_t)n * 128 + c0 + r) * TVn + p0 + tx] = t[tx][r];
}

__global__ __launch_bounds__(256) void txpose_tmaj()
{
    __shared__ float t[32][33];
    int bt = blockIdx.x;
    int t0 = (bt & 3) * 32, c0 = (bt >> 2) * 32;
    int v = blockIdx.y, n = blockIdx.z;
    int tx = threadIdx.x & 31, ty = threadIdx.x >> 5;
    for (int r = ty; r < 32; r += 8)
        t[r][tx] = g_soT[(size_t)n * TVn * 128 + (size_t)((t0 + r) * 25 + v) * 128 + c0 + tx];
    __syncthreads();
    for (int r = ty; r < 32; r += 8)
        g_tmaj[((size_t)(n * 25 + v) * 128 + c0 + r) * 128 + t0 + tx] = t[tx][r];
}

__global__ __launch_bounds__(256)
void satt_kernel(const float* __restrict__ att0, const float* __restrict__ alphas)
{
    int t = blockIdx.x, s = blockIdx.y, n = blockIdx.z;
    __shared__ float qs[32][26], ks[32][26];
    int tid = threadIdx.x;
    const float* qb = g_qkT + (size_t)n * TVn * 192;
    for (int i = tid; i < 832; i += 256) {
        int row = i >> 5, c = i & 31;
        float qv = 0.f, kv = 0.f;
        if (row < 25) {
            qv = qb[(size_t)(t * 25 + row) * 192 + s * 32 + c];
            kv = qb[(size_t)(t * 25 + row) * 192 + 96 + s * 32 + c];
        }
        qs[c][row] = qv;
        ks[c][row] = kv;
    }
    __syncthreads();
    float alpha = alphas[s];
    float* ob = g_atts + (((size_t)(n * 3 + s)) * 128 + t) * 704;
    if (tid < 169) {
        int ti = tid / 13, tj = tid % 13;
        int u0 = ti * 2, v0 = tj * 2;
        float s00 = 0.f, s01 = 0.f, s10 = 0.f, s11 = 0.f;
        #pragma unroll
        for (int c = 0; c < 32; c++) {
            float2 q2 = *(const float2*)&qs[c][u0];
            float2 k2 = *(const float2*)&ks[c][v0];
            s00 += q2.x * k2.x; s01 += q2.x * k2.y;
            s10 += q2.y * k2.x; s11 += q2.y * k2.y;
        }
        float b00 = att0[s * 625 + u0 * 25 + v0];
        float b01 = (v0 + 1 < 25) ? att0[s * 625 + u0 * 25 + v0 + 1] : 0.f;
        float2 o0, o1;
        o0.x = b00 + tanh_ap(s00 * (1.f / 32.f)) * alpha;
        o0.y = (v0 + 1 < 25) ? b01 + tanh_ap(s01 * (1.f / 32.f)) * alpha : 0.f;
        *(float2*)&ob[u0 * 28 + v0] = o0;
        if (u0 + 1 < 25) {
            float b10 = att0[s * 625 + (u0 + 1) * 25 + v0];
            float b11 = (v0 + 1 < 25) ? att0[s * 625 + (u0 + 1) * 25 + v0 + 1] : 0.f;
            o1.x = b10 + tanh_ap(s10 * (1.f / 32.f)) * alpha;
            o1.y = (v0 + 1 < 25) ? b11 + tanh_ap(s11 * (1.f / 32.f)) * alpha : 0.f;
            *(float2*)&ob[(u0 + 1) * 28 + v0] = o1;
        }
    } else if (tid >= 169 && tid < 194) {
        int u = tid - 169;
        *(float2*)&ob[u * 28 + 26] = make_float2(0.f, 0.f);
    }
}

__global__ __launch_bounds__(128)
void ymix_kernel()
{
    int t = blockIdx.x, s = blockIdx.y, n = blockIdx.z;
    __shared__ float4 a4[25][7];
    int c = threadIdx.x;
    const float4* ab4 = (const float4*)(g_atts + (((size_t)(n * 3 + s)) * 128 + t) * 704);
    for (int i = c; i < 175; i += 128) a4[i / 7][i % 7] = ab4[i];
    __syncthreads();
    float xr[25];
    const float* xb = g_xT + (size_t)n * TVn * 128 + (size_t)(t * 25) * 128 + c;
    #pragma unroll
    for (int u = 0; u < 25; u++) xr[u] = xb[u * 128];
    float4 acc[7];
    #pragma unroll
    for (int g = 0; g < 7; g++) acc[g] = make_float4(0.f, 0.f, 0.f, 0.f);
    #pragma unroll
    for (int u = 0; u < 25; u++) {
        float xu = xr[u];
        #pragma unroll
        for (int g = 0; g < 7; g++) {
            float4 av = a4[u][g];
            acc[g].x += xu * av.x; acc[g].y += xu * av.y;
            acc[g].z += xu * av.z; acc[g].w += xu * av.w;
        }
    }
    float* yb = g_yT + (size_t)n * TVn * 384 + (size_t)(t * 25) * 384 + s * 128 + c;
    #pragma unroll
    for (int g = 0; g < 7; g++) {
        const float* ap = (const float*)&acc[g];
        #pragma unroll
        for (int j = 0; j < 4; j++) {
            int v = g * 4 + j;
            if (v < 25) yb[(size_t)v * 384] = ap[j];
        }
    }
}

__global__ void meanv_kernel()
{
    int i = blockIdx.x * blockDim.x + threadIdx.x;
    if (i >= NB * 128 * 128) return;
    int c = i & 127, t = (i >> 7) & 127, n = i >> 14;
    const float* b = g_soT + (size_t)n * TVn * 128 + (size_t)(t * 25) * 128 + c;
    float sum = 0.f;
    #pragma unroll
    for (int v = 0; v < 25; v++) sum += b[v * 128];
    g_sbar[(size_t)n * 16384 + t * 128 + c] = sum * (1.f / 25.f);
}

__global__ __launch_bounds__(256)
void tatt_kernel(const float* __restrict__ af, const float* __restrict__ ab)
{
    int bz = blockIdx.x;
    int n = bz >> 4, s = (bz >> 2) & 3, ug = bz & 3;
    __shared__ float qs[32][129], ksu[32][32];
    int tid = threadIdx.x;
    const float* base = g_qtm + (size_t)n * 32768;
    for (int i = tid; i < 4096; i += 256) {
        int t = i >> 5, c = i & 31;
        qs[c][t] = base[t * 256 + s * 32 + c];
    }
    for (int i = tid; i < 1024; i += 256) {
        int ul = i >> 5, c = i & 31;
        ksu[c][ul] = base[(ug * 32 + ul) * 256 + 128 + s * 32 + c];
    }
    __syncthreads();
    float alpha = (s < 2) ? af[s] : ab[s - 2];
    float* ob = g_att + ((size_t)(n * 4 + s)) * 16384;
    for (int idx = tid; idx < 4096; idx += 256) {
        int ul = idx >> 7, t = idx & 127;
        int u = ug * 32 + ul;
        float sum = 0.f;
        #pragma unroll
        for (int c = 0; c < 32; c++) sum += qs[c][t] * ksu[c][ul];
        float v = tanh_ap(sum * (1.f / 32.f)) * alpha;
        bool keep = (s < 2) ? (t >= u) : (u >= t);
        ob[u * 128 + t] = keep ? v : 0.f;
    }
}

// ---------------- host launcher ----------------
extern "C" void kernel_launch(void* const* d_in, const int* in_sizes, int n_in,
                              void* d_out, int out_size)
{
    const float* x       = (const float*)d_in[0];
    const float* w_in_s  = (const float*)d_in[1];
    const float* b_in_s  = (const float*)d_in[2];
    const float* att0s   = (const float*)d_in[3];
    const float* alphas  = (const float*)d_in[4];
    const float* w_out_s = (const float*)d_in[5];
    const float* b_out_s = (const float*)d_in[6];
    const float* g_out_s = (const float*)d_in[7];
    const float* be_out_s= (const float*)d_in[8];
    const float* w_ff_s  = (const float*)d_in[9];
    const float* b_ff_s  = (const float*)d_in[10];
    const float* g_ff_s  = (const float*)d_in[11];
    const float* be_ff_s = (const float*)d_in[12];
    const float* w_in_t  = (const float*)d_in[13];
    const float* b_in_t  = (const float*)d_in[14];
    const float* al_f    = (const float*)d_in[15];
    const float* al_b    = (const float*)d_in[16];
    const float* w_out_t = (const float*)d_in[17];
    const float* b_out_t = (const float*)d_in[18];
    const float* g_out_t = (const float*)d_in[19];
    const float* be_out_t= (const float*)d_in[20];
    const float* w_ff_t  = (const float*)d_in[21];
    const float* b_ff_t  = (const float*)d_in[22];
    const float* g_ff_t  = (const float*)d_in[23];
    const float* be_ff_t = (const float*)d_in[24];
    const float* w_tcn   = (const float*)d_in[25];
    const float* b_tcn   = (const float*)d_in[26];
    const float* g_tcn   = (const float*)d_in[27];
    const float* be_tcn  = (const float*)d_in[28];
    float* out = (float*)d_out;

    float *wp, *xT, *qkT, *yT, *s1T, *soT, *sbar, *qtm, *att, *tmaj, *zT, *toT, *tnc;
    cudaGetSymbolAddress((void**)&wp,   g_wp);
    cudaGetSymbolAddress((void**)&xT,   g_xT);
    cudaGetSymbolAddress((void**)&qkT,  g_qkT);
    cudaGetSymbolAddress((void**)&yT,   g_yT);
    cudaGetSymbolAddress((void**)&s1T,  g_s1T);
    cudaGetSymbolAddress((void**)&soT,  g_soT);
    cudaGetSymbolAddress((void**)&sbar, g_sbar);
    cudaGetSymbolAddress((void**)&qtm,  g_qtm);
    cudaGetSymbolAddress((void**)&att,  g_att);
    cudaGetSymbolAddress((void**)&tmaj, g_tmaj);
    cudaGetSymbolAddress((void**)&zT,   g_zT);
    cudaGetSymbolAddress((void**)&toT,  g_toT);
    cudaGetSymbolAddress((void**)&tnc,  g_tnc);

    auto G1w = mma_gemm_w<0,0,0,true,false,false,false,true>;   // qk
    auto G2w = mma_gemm_w<0,0,0,true,true,true,true,false>;     // bn+res+lrelu
    auto G4w = mma_gemm_w<2,0,3,false,false,false,false,false>; // temporal mix -> zT
    auto G5w = mma_gemm_w<0,1,1,true,true,true,true,false>;     // TCN, NCHW out
    auto G3  = mma_gemm<true,false>;                            // qtm (bias only)
    cudaFuncSetAttribute(G1w, cudaFuncAttributeMaxDynamicSharedMemorySize, SMEMW);
    cudaFuncSetAttribute(G2w, cudaFuncAttributeMaxDynamicSharedMemorySize, SMEMW);
    cudaFuncSetAttribute(G4w, cudaFuncAttributeMaxDynamicSharedMemorySize, SMEMW);
    cudaFuncSetAttribute(G5w, cudaFuncAttributeMaxDynamicSharedMemorySize, SMEMW);
    cudaFuncSetAttribute(G3,  cudaFuncAttributeMaxDynamicSharedMemorySize, SMEMSZ);

    // [0] pack, [1][2] transpose x
    pack_all<<<(W_TOTAL+255)/256,256>>>(w_in_s, w_out_s, w_ff_s, w_in_t, w_out_t, w_ff_t, w_tcn);
    txpose_x<<<dim3(100,4,16),256>>>(x, 0);
    txpose_x<<<dim3(100,4,16),256>>>(x, 16);

    // [3] qk = W_in_s @ x + b  <- ncu profiles this
    G1w<<<dim3(13,2,NB),512,SMEMW>>>(wp+OFF_WINS, xT, qkT,
        b_in_s, nullptr, nullptr, nullptr, 128, 128, 192, 192, 4, TVn);

    // [4] satt, [5] ymix
    satt_kernel<<<dim3(128,3,NB),256>>>(att0s, alphas);
    ymix_kernel<<<dim3(128,3,NB),128>>>();

    // [6] s1 = lrelu(x + bn(W_out_s @ y + b))  K=384
    G2w<<<dim3(13,1,NB),512,SMEMW>>>(wp+OFF_WOUTS, yT, s1T,
        b_out_s, g_out_s, be_out_s, xT, 384, 384, 128, 128, 12, TVn);

    // [7] sout = lrelu(x + bn(W_ff_s @ s1 + b))
    G2w<<<dim3(13,1,NB),512,SMEMW>>>(wp+OFF_WFFS, s1T, soT,
        b_ff_s, g_ff_s, be_ff_s, xT, 128, 128, 128, 128, 4, TVn);

    // [8] meanv, [9] qtm
    meanv_kernel<<<(NB*128*128+255)/256,256>>>();
    G3<<<dim3(1,2,NB),256,SMEMSZ>>>(wp+OFF_WINT, sbar, qtm,
        b_in_t, 128, 128, 256, 256, 4, 128);

    // [10] tatt
    tatt_kernel<<<NB*16,256>>>(al_f, al_b);

    // [11] sout -> tmaj
    txpose_tmaj<<<dim3(16,25,NB),256>>>();

    // [12] z (temporal mix): per (n,s) M=128 N=3200 K=128
    G4w<<<dim3(13,1,NB*4),512,SMEMW>>>(att, tmaj, zT,
        nullptr, nullptr, nullptr, nullptr, 128, 128, 512, 128, 4, TVn);

    // [13] t1 = lrelu(sout + bn(W_out_t @ z + b))  K=512
    G2w<<<dim3(13,1,NB),512,SMEMW>>>(wp+OFF_WOUTT, zT, s1T,
        b_out_t, g_out_t, be_out_t, soT, 512, 512, 128, 128, 16, TVn);

    // [14] tout = lrelu(sout + bn(W_ff_t @ t1 + b))
    G2w<<<dim3(13,1,NB),512,SMEMW>>>(wp+OFF_WFFT, s1T, toT,
        b_ff_t, g_ff_t, be_ff_t, soT, 128, 128, 128, 128, 4, TVn);

    // [15] toT -> NCHW
    txpose_inv<<<dim3(100,4,NB),256>>>();

    // [16] out = lrelu(tout + bn(tcn7(tout)+b))  K=896 im2col
    G5w<<<dim3(13,1,NB),512,SMEMW>>>(wp+OFF_WTCN, toT, out,
        b_tcn, g_tcn, be_tcn, tnc, 896, 128, 128, 128, 28, TVn);
}

// round 17
// speedup vs baseline: 1.2413x; 1.2413x over previous
#include <cuda_runtime.h>
#include <cuda.h>
#include <cstdint>
#include <math.h>

#define NB 32
#define TVn 3200
#define BN_INV 0.9999950000374997f

// ---------------- scratch ----------------
__device__ float g_wp  [327680];
__device__ float g_xT  [(size_t)NB*TVn*128];
__device__ float g_qkT [(size_t)NB*TVn*192];
__device__ float g_atts[(size_t)NB*3*128*704];
__device__ float g_yT  [(size_t)NB*TVn*384];
__device__ float g_s1T [(size_t)NB*TVn*128];
__device__ float g_soT [(size_t)NB*TVn*128];
__device__ float g_sbar[(size_t)NB*128*128];
__device__ float g_qtm [(size_t)NB*128*256];
__device__ float g_att [(size_t)NB*4*128*128];
__device__ float g_tmaj[(size_t)NB*25*128*128];
__device__ float g_zT  [(size_t)NB*TVn*512];
__device__ float g_toT [(size_t)NB*TVn*128];
__device__ float g_tnc [(size_t)NB*128*TVn];
__device__ __align__(128) CUtensorMap g_tm[13];

#define OFF_WINS  0
#define OFF_WOUTS 32768
#define OFF_WFFS  81920
#define OFF_WINT  98304
#define OFF_WOUTT 131072
#define OFF_WFFT  196608
#define OFF_WTCN  212992
#define W_TOTAL   327680

// narrow kernel smem (G3)
#define RS     36
#define BOFF_F 4608
#define STG_F  9216
#define NSTAGE 3
#define SMEMSZ (STG_F * NSTAGE * 4)

// wide TMA kernel smem: stage = A 16KB + B 32KB (SW128 layout), 4 stages + mbarriers
#define STGB   49152
#define NSTW   4
#define SMEMW  (STGB * NSTW + 64)       // 196672 B

// ---------------- helpers ----------------
__device__ __forceinline__ uint32_t smem_u32(const void* p){
    uint32_t a;
    asm("{ .reg .u64 t; cvta.to.shared.u64 t, %1; cvt.u32.u64 %0, t; }" : "=r"(a) : "l"(p));
    return a;
}
__device__ __forceinline__ uint32_t f2tf32(float f){
    uint32_t r; asm("cvt.rna.tf32.f32 %0, %1;" : "=r"(r) : "f"(f)); return r;
}
__device__ __forceinline__ float tanh_ap(float x){
    float r; asm("tanh.approx.f32 %0, %1;" : "=f"(r) : "f"(x)); return r;
}
__device__ __forceinline__ uint32_t swz(uint32_t off){ return off ^ ((off >> 3) & 0x70); }
__device__ __forceinline__ void mma_tf32(float* d, const uint32_t* a, const uint32_t* b){
    asm volatile("mma.sync.aligned.m16n8k8.row.col.f32.tf32.tf32.f32 "
        "{%0,%1,%2,%3}, {%4,%5,%6,%7}, {%8,%9}, {%0,%1,%2,%3};"
        : "+f"(d[0]), "+f"(d[1]), "+f"(d[2]), "+f"(d[3])
        : "r"(a[0]), "r"(a[1]), "r"(a[2]), "r"(a[3]), "r"(b[0]), "r"(b[1]));
}
#define MBWAIT(bar, ph) \
    asm volatile("{\n\t.reg .pred P;\n\tW%=:\n\tmbarrier.try_wait.parity.shared::cta.b64 P, [%0], %1, 0x989680;\n\t@P bra D%=;\n\tbra W%=;\n\tD%=:\n\t}" \
                 :: "r"(bar), "r"(ph) : "memory")

// ================= narrow kernel (G3 only, cp.async path) =================
__device__ __forceinline__ void compute_chunk(uint32_t stage_b, int lane,
                                              int wm, int wn, float acc[4][4][4]){
    const int arow = (lane & 7) + ((lane >> 3) & 1) * 8;
    const uint32_t aoff = ((lane >> 4) & 1) * 16;
    const int brow = lane & 7;
    const uint32_t boff = ((lane >> 3) & 1) * 16;
    const uint32_t abase = stage_b + (uint32_t)((wm + arow) * RS) * 4u + aoff;
    const uint32_t bbase = stage_b + (uint32_t)(BOFF_F + (wn + brow) * RS) * 4u + boff;
    #pragma unroll
    for (int k8 = 0; k8 < 4; k8++){
        uint32_t af[4][4], bf[4][2];
        #pragma unroll
        for (int mt = 0; mt < 4; mt++){
            uint32_t ad = abase + (uint32_t)(mt * 16 * RS) * 4u + k8 * 32;
            asm volatile("ldmatrix.sync.aligned.m8n8.x4.shared.b16 {%0,%1,%2,%3}, [%4];"
                : "=r"(af[mt][0]), "=r"(af[mt][1]), "=r"(af[mt][2]), "=r"(af[mt][3])
                : "r"(ad));
        }
        #pragma unroll
        for (int nt = 0; nt < 4; nt++){
            uint32_t bd = bbase + (uint32_t)(nt * 8 * RS) * 4u + k8 * 32;
            asm volatile("ldmatrix.sync.aligned.m8n8.x2.shared.b16 {%0,%1}, [%2];"
                : "=r"(bf[nt][0]), "=r"(bf[nt][1])
                : "r"(bd));
        }
        #pragma unroll
        for (int mt = 0; mt < 4; mt++)
            #pragma unroll
            for (int nt = 0; nt < 4; nt++)
                mma_tf32(acc[mt][nt], af[mt], bf[nt]);
    }
}

template<bool BIAS,bool PRED>
__global__ __launch_bounds__(256,2)
void mma_gemm(const float* __restrict__ A, const float* __restrict__ Bp,
              float* __restrict__ Cp, const float* __restrict__ bias,
              int Ka, int Bld, int ldc, int Mvalid, int nch, int Np)
{
    extern __shared__ uint32_t sm[];
    const uint32_t sbw = smem_u32(sm);
    const int tid = threadIdx.x, lane = tid & 31, wid = tid >> 5;
    const int wm = (wid >> 2) * 64, wn = (wid & 3) * 32;
    const int lq = lane >> 2, klo = lane & 3;

    const int n = blockIdx.z;
    const int m0 = blockIdx.y * 128;
    const int p0 = blockIdx.x * 128;
    const float* Bb = Bp + (size_t)n * Np * Bld;

    const int r = tid & 127, kh = (tid >> 7) * 16;
    const float* parow = A + (size_t)(m0 + r) * Ka + kh;

    float acc[4][4][4];
    #pragma unroll
    for (int a = 0; a < 4; a++)
        #pragma unroll
        for (int b = 0; b < 4; b++)
            #pragma unroll
            for (int c = 0; c < 4; c++) acc[a][b][c] = 0.f;

#define ISSUE(cc, stg) {                                                         \
        const int k0_ = (cc) * 32;                                               \
        const float* asrc_ = parow + k0_;                                        \
        const float* bsrc_ = Bb + (size_t)(p0 + r) * Bld + k0_ + kh;             \
        const uint32_t ad_ = sbw + 4u * ((stg) * STG_F + r * RS + kh);           \
        const uint32_t bd_ = sbw + 4u * ((stg) * STG_F + BOFF_F + r * RS + kh);  \
        _Pragma("unroll")                                                        \
        for (int i = 0; i < 4; i++){                                             \
            asm volatile("cp.async.cg.shared.global [%0], [%1], 16;"             \
                         :: "r"(ad_ + 16u*i), "l"(asrc_ + i*4) : "memory");      \
            asm volatile("cp.async.cg.shared.global [%0], [%1], 16;"             \
                         :: "r"(bd_ + 16u*i), "l"(bsrc_ + i*4) : "memory");      \
        } }

    ISSUE(0, 0)
    asm volatile("cp.async.commit_group;" ::: "memory");
    ISSUE(1, 1)
    asm volatile("cp.async.commit_group;" ::: "memory");

    for (int c = 0; c < nch; c++) {
        asm volatile("cp.async.wait_group 1;" ::: "memory");
        __syncthreads();
        compute_chunk(sbw + 4u * ((c % NSTAGE) * STG_F), lane, wm, wn, acc);
        const int nc = c + 2;
        if (nc < nch) { ISSUE(nc, nc % NSTAGE) }
        asm volatile("cp.async.commit_group;" ::: "memory");
    }
#undef ISSUE

    asm volatile("cp.async.wait_group 0;" ::: "memory");
    __syncthreads();
    float* smf = reinterpret_cast<float*>(sm);

    #pragma unroll
    for (int mt = 0; mt < 4; mt++)
        #pragma unroll
        for (int h = 0; h < 2; h++)
            #pragma unroll
            for (int nt = 0; nt < 4; nt++)
                #pragma unroll
                for (int q = 0; q < 2; q++) {
                    const int m = wm + mt*16 + lq + h*8;
                    const int col = wn + nt*8 + klo*2 + q;
                    smf[col*132 + m] = acc[mt][nt][h*2 + q];
                }
    __syncthreads();

    #pragma unroll
    for (int it = 0; it < 16; it++) {
        const int idx = it*256 + tid;
        const int col = idx >> 5, m4 = (idx & 31) * 4;
        const int mg0 = m0 + m4;
        if (PRED && mg0 >= Mvalid) continue;
        float4 v4 = *(float4*)&smf[col*132 + m4];
        float vv[4] = {v4.x, v4.y, v4.z, v4.w};
        float4 b4;
        if (BIAS) b4 = *(const float4*)(bias + mg0);
        const float* bp = (const float*)&b4;
        float4 o4; float* op = (float*)&o4;
        #pragma unroll
        for (int j = 0; j < 4; j++) {
            float v = vv[j];
            if (BIAS) v += bp[j];
            op[j] = v;
        }
        *(float4*)(Cp + ((size_t)n*Np + p0 + col)*ldc + mg0) = o4;
    }
}

// ================= wide TMA kernel: 128M x 256N, SW128 stages =================
__device__ __forceinline__ void compute_chunk_w(uint32_t stage_b, int lane,
                                                int wm, int wn, float acc[2][8][4]){
    const int arow = (lane & 7) + ((lane >> 3) & 1) * 8;
    const uint32_t aoff = ((lane >> 4) & 1) * 16;
    const int brow = (lane & 7) + ((lane >> 4) & 1) * 8;
    const uint32_t boff = ((lane >> 3) & 1) * 16;
    #pragma unroll
    for (int k8 = 0; k8 < 4; k8++){
        uint32_t af[2][4], bf[8][2];
        #pragma unroll
        for (int mt = 0; mt < 2; mt++){
            uint32_t off = (uint32_t)(wm + arow + mt*16) * 128u + k8*32 + aoff;
            uint32_t ad = stage_b + swz(off);
            asm volatile("ldmatrix.sync.aligned.m8n8.x4.shared.b16 {%0,%1,%2,%3}, [%4];"
                : "=r"(af[mt][0]), "=r"(af[mt][1]), "=r"(af[mt][2]), "=r"(af[mt][3])
                : "r"(ad));
        }
        #pragma unroll
        for (int ng = 0; ng < 4; ng++){
            uint32_t off = (uint32_t)(wn + brow + ng*16) * 128u + k8*32 + boff;
            uint32_t bd = stage_b + 16384u + swz(off);
            asm volatile("ldmatrix.sync.aligned.m8n8.x4.shared.b16 {%0,%1,%2,%3}, [%4];"
                : "=r"(bf[2*ng][0]), "=r"(bf[2*ng][1]), "=r"(bf[2*ng+1][0]), "=r"(bf[2*ng+1][1])
                : "r"(bd));
        }
        #pragma unroll
        for (int mt = 0; mt < 2; mt++)
            #pragma unroll
            for (int nt = 0; nt < 8; nt++)
                mma_tf32(acc[mt][nt], af[mt], bf[nt]);
    }
}

template<int ZM,int BSHIFT,int CM,bool BIAS,bool BNORM,bool RES,bool LRELU,bool PRED>
__global__ __launch_bounds__(512,1)
void mma_gemm_w(const void* __restrict__ tmA, const void* __restrict__ tmB,
                float* __restrict__ Cp,
                const float* __restrict__ bias, const float* __restrict__ gam,
                const float* __restrict__ bet, const float* __restrict__ resT,
                int ldc, int Mvalid, int nch, int Np)
{
    extern __shared__ uint32_t sm[];
    const uint32_t sbw = smem_u32(sm);
    const uint32_t mbar = sbw + (uint32_t)(STGB * NSTW);
    const int tid = threadIdx.x, lane = tid & 31, wid = tid >> 5;
    const int wm = (wid >> 2) * 32, wn = (wid & 3) * 64;
    const int lq = lane >> 2, klo = lane & 3;

    int n, s4 = 0;
    if (ZM == 0) { n = blockIdx.z; }
    else { n = blockIdx.z >> 2; s4 = blockIdx.z & 3; }
    const int m0 = blockIdx.y * 128;
    const int p0 = blockIdx.x * 256;

    if (tid == 0) {
        #pragma unroll
        for (int s = 0; s < NSTW; s++)
            asm volatile("mbarrier.init.shared.b64 [%0], 1;" :: "r"(mbar + s*8) : "memory");
    }
    __syncthreads();

    float acc[2][8][4];
    #pragma unroll
    for (int a = 0; a < 2; a++)
        #pragma unroll
        for (int b = 0; b < 8; b++)
            #pragma unroll
            for (int c = 0; c < 4; c++) acc[a][b][c] = 0.f;

#define ISSUET(cc) {                                                             \
        const int stg_ = (cc) & 3;                                               \
        const uint32_t bar_ = mbar + stg_ * 8;                                   \
        if (tid == 0) {                                                          \
            int k0_ = (cc) * 32, k0B_, sh_;                                      \
            if (BSHIFT){ int j_ = (cc) >> 2; k0B_ = ((cc) & 3) * 32; sh_ = (j_-3)*25; } \
            else { k0B_ = k0_; sh_ = 0; }                                        \
            asm volatile("mbarrier.arrive.expect_tx.shared.b64 _, [%0], %1;"     \
                         :: "r"(bar_), "r"(49152u) : "memory");                  \
            const uint32_t ad_ = sbw + (uint32_t)(stg_ * STGB);                  \
            const uint32_t bd_ = ad_ + 16384u;                                   \
            if (ZM == 2)                                                         \
                asm volatile("cp.async.bulk.tensor.3d.shared::cta.global.tile.mbarrier::complete_tx::bytes [%0], [%1, {%2, %3, %4}], [%5];" \
                    :: "r"(ad_), "l"(tmA), "r"(k0_), "r"(m0), "r"((int)blockIdx.z), "r"(bar_) : "memory"); \
            else                                                                 \
                asm volatile("cp.async.bulk.tensor.2d.shared::cta.global.tile.mbarrier::complete_tx::bytes [%0], [%1, {%2, %3}], [%4];" \
                    :: "r"(ad_), "l"(tmA), "r"(k0_), "r"(m0), "r"(bar_) : "memory"); \
            asm volatile("cp.async.bulk.tensor.3d.shared::cta.global.tile.mbarrier::complete_tx::bytes [%0], [%1, {%2, %3, %4}], [%5];" \
                :: "r"(bd_), "l"(tmB), "r"(k0B_), "r"(p0 + sh_), "r"(n), "r"(bar_) : "memory"); \
        } }

    ISSUET(0)
    ISSUET(1)
    ISSUET(2)

    for (int c = 0; c < nch; c++) {
        MBWAIT(mbar + (c & 3) * 8, (c >> 2) & 1);
        compute_chunk_w(sbw + (uint32_t)((c & 3) * STGB), lane, wm, wn, acc);
        __syncthreads();
        const int nc = c + 3;
        if (nc < nch) { ISSUET(nc) }
    }
#undef ISSUET

    // ---- single-pass epilogue over freed stages ----
    float* ep = reinterpret_cast<float*>(sm);
    #pragma unroll
    for (int mt = 0; mt < 2; mt++)
        #pragma unroll
        for (int h = 0; h < 2; h++)
            #pragma unroll
            for (int nt = 0; nt < 8; nt++)
                #pragma unroll
                for (int q = 0; q < 2; q++) {
                    const int m = wm + mt*16 + lq + h*8;
                    const int cl = wn + nt*8 + klo*2 + q;
                    if (CM == 0) ep[cl*132 + m] = acc[mt][nt][h*2 + q];
                    else         ep[m*260 + cl] = acc[mt][nt][h*2 + q];
                }
    __syncthreads();

    #pragma unroll
    for (int it = 0; it < 16; it++) {
        const int idx = it*512 + tid;
        if (CM == 0) {
            const int col = idx >> 5, m4 = (idx & 31) * 4;
            const int mg0 = m0 + m4;
            if (PRED && mg0 >= Mvalid) continue;
            if (p0 + col >= Np) continue;
            float4 v4 = *(float4*)&ep[col*132 + m4];
            float vv[4] = {v4.x, v4.y, v4.z, v4.w};
            float4 b4, g4, e4, r4;
            if (BIAS)  b4 = *(const float4*)(bias + mg0);
            if (BNORM){ g4 = *(const float4*)(gam + mg0); e4 = *(const float4*)(bet + mg0); }
            if (RES)   r4 = *(const float4*)(resT + ((size_t)n*Np + p0 + col)*128 + mg0);
            const float* bp = (const float*)&b4; const float* gp = (const float*)&g4;
            const float* epp = (const float*)&e4; const float* rp = (const float*)&r4;
            float4 o4; float* op = (float*)&o4;
            #pragma unroll
            for (int j = 0; j < 4; j++) {
                float v = vv[j];
                if (BIAS)  v += bp[j];
                if (BNORM) v = v * (gp[j] * BN_INV) + epp[j];
                if (RES)   v += rp[j];
                if (LRELU) v = v > 0.f ? v : 0.1f * v;
                op[j] = v;
            }
            *(float4*)(Cp + ((size_t)n*Np + p0 + col)*ldc + mg0) = o4;
        } else if (CM == 1) {
            const int m = idx >> 6, c4l = (idx & 63) * 4;
            const int mg = m0 + m;
            if (p0 + c4l >= Np) continue;
            float4 v4 = *(float4*)&ep[m*260 + c4l];
            float vv[4] = {v4.x, v4.y, v4.z, v4.w};
            float bi = BIAS ? bias[mg] : 0.f;
            float sc = BNORM ? gam[mg] * BN_INV : 1.f;
            float sh = BNORM ? bet[mg] : 0.f;
            float4 r4;
            if (RES) r4 = *(const float4*)(resT + ((size_t)(n*128 + mg))*TVn + p0 + c4l);
            const float* rp = (const float*)&r4;
            float4 o4; float* op = (float*)&o4;
            #pragma unroll
            for (int j = 0; j < 4; j++) {
                float v = vv[j] + bi;
                if (BNORM) v = v * sc + sh;
                if (RES)   v += rp[j];
                if (LRELU) v = v > 0.f ? v : 0.1f * v;
                op[j] = v;
            }
            *(float4*)(Cp + ((size_t)(n*128 + mg))*TVn + p0 + c4l) = o4;
        } else {
            const int m = idx >> 6, c4l = (idx & 63) * 4;
            const int gc = p0 + c4l;
            if (gc >= Np) continue;
            const int vv25 = gc >> 7, cmod = gc & 127;
            float4 v4 = *(float4*)&ep[m*260 + c4l];
            *(float4*)(Cp + ((size_t)n*TVn + (size_t)m*25 + vv25)*512 + s4*128 + cmod) = v4;
        }
    }
}

// ---------------- prep kernels ----------------
__global__ void pack_all(const float* __restrict__ w_in_s, const float* __restrict__ w_out_s,
                         const float* __restrict__ w_ff_s, const float* __restrict__ w_in_t,
                         const float* __restrict__ w_out_t, const float* __restrict__ w_ff_t,
                         const float* __restrict__ w_tcn)
{
    int idx = blockIdx.x * blockDim.x + threadIdx.x;
    if (idx >= W_TOTAL) return;
    const float* src; int off, Msrc, K, tcn = 0;
    if      (idx < OFF_WOUTS){ src = w_in_s;  off = OFF_WINS;  Msrc = 192; K = 128; }
    else if (idx < OFF_WINT) { if (idx < OFF_WFFS){ src = w_out_s; off = OFF_WOUTS; Msrc = 128; K = 384; }
                               else              { src = w_ff_s;  off = OFF_WFFS;  Msrc = 128; K = 128; } }
    else if (idx < OFF_WOUTT){ src = w_in_t;  off = OFF_WINT;  Msrc = 256; K = 128; }
    else if (idx < OFF_WFFT) { src = w_out_t; off = OFF_WOUTT; Msrc = 128; K = 512; }
    else if (idx < OFF_WTCN) { src = w_ff_t;  off = OFF_WFFT;  Msrc = 128; K = 128; }
    else                     { src = w_tcn;   off = OFF_WTCN;  Msrc = 128; K = 896; tcn = 1; }
    int local = idx - off;
    int mrow = local / K, k = local - mrow * K;
    float v = 0.f;
    if (mrow < Msrc) {
        if (tcn) { int j = k >> 7, c = k & 127; v = src[(mrow * 128 + c) * 7 + j]; }
        else     { v = src[(size_t)mrow * K + k]; }
    }
    g_wp[idx] = __uint_as_float(f2tf32(v));
}

__global__ __launch_bounds__(256) void txpose_x(const float* __restrict__ x, int nbase)
{
    __shared__ float t[32][33];
    int p0 = blockIdx.x * 32, c0 = blockIdx.y * 32, n = nbase + blockIdx.z;
    int tx = threadIdx.x & 31, ty = threadIdx.x >> 5;
    for (int r = ty; r < 32; r += 8)
        t[r][tx] = x[((size_t)n * 128 + c0 + r) * TVn + p0 + tx];
    __syncthreads();
    for (int r = ty; r < 32; r += 8)
        g_xT[(size_t)n * TVn * 128 + (size_t)(p0 + r) * 128 + c0 + tx] = t[tx][r];
}

__global__ __launch_bounds__(256) void txpose_inv()
{
    __shared__ float t[32][33];
    int p0 = blockIdx.x * 32, c0 = blockIdx.y * 32, n = blockIdx.z;
    int tx = threadIdx.x & 31, ty = threadIdx.x >> 5;
    for (int r = ty; r < 32; r += 8)
        t[r][tx] = g_toT[((size_t)n * TVn + p0 + r) * 128 + c0 + tx];
    __syncthreads();
    for (int r = ty; r < 32; r += 8)
        g_tnc[((size_t)n * 128 + c0 + r) * TVn + p0 + tx] = t[tx][r];
}

__global__ __launch_bounds__(256) void txpose_tmaj()
{
    __shared__ float t[32][33];
    int bt = blockIdx.x;
    int t0 = (bt & 3) * 32, c0 = (bt >> 2) * 32;
    int v = blockIdx.y, n = blockIdx.z;
    int tx = threadIdx.x & 31, ty = threadIdx.x >> 5;
    for (int r = ty; r < 32; r += 8)
        t[r][tx] = g_soT[(size_t)n * TVn * 128 + (size_t)((t0 + r) * 25 + v) * 128 + c0 + tx];
    __syncthreads();
    for (int r = ty; r < 32; r += 8)
        g_tmaj[((size_t)(n * 25 + v) * 128 + c0 + r) * 128 + t0 + tx] = t[tx][r];
}

__global__ __launch_bounds__(256)
void satt_kernel(const float* __restrict__ att0, const float* __restrict__ alphas)
{
    int t = blockIdx.x, s = blockIdx.y, n = blockIdx.z;
    __shared__ float qs[32][26], ks[32][26];
    int tid = threadIdx.x;
    const float* qb = g_qkT + (size_t)n * TVn * 192;
    for (int i = tid; i < 832; i += 256) {
        int row = i >> 5, c = i & 31;
        float qv = 0.f, kv = 0.f;
        if (row < 25) {
            qv = qb[(size_t)(t * 25 + row) * 192 + s * 32 + c];
            kv = qb[(size_t)(t * 25 + row) * 192 + 96 + s * 32 + c];
        }
        qs[c][row] = qv;
        ks[c][row] = kv;
    }
    __syncthreads();
    float alpha = alphas[s];
    float* ob = g_atts + (((size_t)(n * 3 + s)) * 128 + t) * 704;
    if (tid < 169) {
        int ti = tid / 13, tj = tid % 13;
        int u0 = ti * 2, v0 = tj * 2;
        float s00 = 0.f, s01 = 0.f, s10 = 0.f, s11 = 0.f;
        #pragma unroll
        for (int c = 0; c < 32; c++) {
            float2 q2 = *(const float2*)&qs[c][u0];
            float2 k2 = *(const float2*)&ks[c][v0];
            s00 += q2.x * k2.x; s01 += q2.x * k2.y;
            s10 += q2.y * k2.x; s11 += q2.y * k2.y;
        }
        float b00 = att0[s * 625 + u0 * 25 + v0];
        float b01 = (v0 + 1 < 25) ? att0[s * 625 + u0 * 25 + v0 + 1] : 0.f;
        float2 o0, o1;
        o0.x = b00 + tanh_ap(s00 * (1.f / 32.f)) * alpha;
        o0.y = (v0 + 1 < 25) ? b01 + tanh_ap(s01 * (1.f / 32.f)) * alpha : 0.f;
        *(float2*)&ob[u0 * 28 + v0] = o0;
        if (u0 + 1 < 25) {
            float b10 = att0[s * 625 + (u0 + 1) * 25 + v0];
            float b11 = (v0 + 1 < 25) ? att0[s * 625 + (u0 + 1) * 25 + v0 + 1] : 0.f;
            o1.x = b10 + tanh_ap(s10 * (1.f / 32.f)) * alpha;
            o1.y = (v0 + 1 < 25) ? b11 + tanh_ap(s11 * (1.f / 32.f)) * alpha : 0.f;
            *(float2*)&ob[(u0 + 1) * 28 + v0] = o1;
        }
    } else if (tid >= 169 && tid < 194) {
        int u = tid - 169;
        *(float2*)&ob[u * 28 + 26] = make_float2(0.f, 0.f);
    }
}

__global__ __launch_bounds__(128)
void ymix_kernel()
{
    int t = blockIdx.x, s = blockIdx.y, n = blockIdx.z;
    __shared__ float4 a4[25][7];
    int c = threadIdx.x;
    const float4* ab4 = (const float4*)(g_atts + (((size_t)(n * 3 + s)) * 128 + t) * 704);
    for (int i = c; i < 175; i += 128) a4[i / 7][i % 7] = ab4[i];
    __syncthreads();
    float xr[25];
    const float* xb = g_xT + (size_t)n * TVn * 128 + (size_t)(t * 25) * 128 + c;
    #pragma unroll
    for (int u = 0; u < 25; u++) xr[u] = xb[u * 128];
    float4 acc[7];
    #pragma unroll
    for (int g = 0; g < 7; g++) acc[g] = make_float4(0.f, 0.f, 0.f, 0.f);
    #pragma unroll
    for (int u = 0; u < 25; u++) {
        float xu = xr[u];
        #pragma unroll
        for (int g = 0; g < 7; g++) {
            float4 av = a4[u][g];
            acc[g].x += xu * av.x; acc[g].y += xu * av.y;
            acc[g].z += xu * av.z; acc[g].w += xu * av.w;
        }
    }
    float* yb = g_yT + (size_t)n * TVn * 384 + (size_t)(t * 25) * 384 + s * 128 + c;
    #pragma unroll
    for (int g = 0; g < 7; g++) {
        const float* ap = (const float*)&acc[g];
        #pragma unroll
        for (int j = 0; j < 4; j++) {
            int v = g * 4 + j;
            if (v < 25) yb[(size_t)v * 384] = ap[j];
        }
    }
}

__global__ void meanv_kernel()
{
    int i = blockIdx.x * blockDim.x + threadIdx.x;
    if (i >= NB * 128 * 128) return;
    int c = i & 127, t = (i >> 7) & 127, n = i >> 14;
    const float* b = g_soT + (size_t)n * TVn * 128 + (size_t)(t * 25) * 128 + c;
    float sum = 0.f;
    #pragma unroll
    for (int v = 0; v < 25; v++) sum += b[v * 128];
    g_sbar[(size_t)n * 16384 + t * 128 + c] = sum * (1.f / 25.f);
}

__global__ __launch_bounds__(256)
void tatt_kernel(const float* __restrict__ af, const float* __restrict__ ab)
{
    int bz = blockIdx.x;
    int n = bz >> 4, s = (bz >> 2) & 3, ug = bz & 3;
    __shared__ float qs[32][129], ksu[32][32];
    int tid = threadIdx.x;
    const float* base = g_qtm + (size_t)n * 32768;
    for (int i = tid; i < 4096; i += 256) {
        int t = i >> 5, c = i & 31;
        qs[c][t] = base[t * 256 + s * 32 + c];
    }
    for (int i = tid; i < 1024; i += 256) {
        int ul = i >> 5, c = i & 31;
        ksu[c][ul] = base[(ug * 32 + ul) * 256 + 128 + s * 32 + c];
    }
    __syncthreads();
    float alpha = (s < 2) ? af[s] : ab[s - 2];
    float* ob = g_att + ((size_t)(n * 4 + s)) * 16384;
    for (int idx = tid; idx < 4096; idx += 256) {
        int ul = idx >> 7, t = idx & 127;
        int u = ug * 32 + ul;
        float sum = 0.f;
        #pragma unroll
        for (int c = 0; c < 32; c++) sum += qs[c][t] * ksu[c][ul];
        float v = tanh_ap(sum * (1.f / 32.f)) * alpha;
        bool keep = (s < 2) ? (t >= u) : (u >= t);
        ob[u * 128 + t] = keep ? v : 0.f;
    }
}

// ---------------- host: tensormap encode via cudart driver entry point ----------
typedef CUresult (*PFN_tmEnc)(CUtensorMap*, CUtensorMapDataType, cuuint32_t, void*,
                              const cuuint64_t*, const cuuint64_t*, const cuuint32_t*,
                              const cuuint32_t*, CUtensorMapInterleave, CUtensorMapSwizzle,
                              CUtensorMapL2promotion, CUtensorMapFloatOOBfill);

static PFN_tmEnc get_enc(){
    void* fn = nullptr;
    cudaDriverEntryPointQueryResult st;
    cudaGetDriverEntryPoint("cuTensorMapEncodeTiled", &fn, cudaEnableDefault, &st);
    return (PFN_tmEnc)fn;
}
static void enc_a(PFN_tmEnc E, CUtensorMap* m, void* base, uint64_t w, uint64_t h){
    cuuint64_t dims[2] = {w, h};
    cuuint64_t strides[1] = {w * 4};
    cuuint32_t box[2] = {32, 128};
    cuuint32_t es[2] = {1, 1};
    E(m, CU_TENSOR_MAP_DATA_TYPE_FLOAT32, 2, base, dims, strides, box, es,
      CU_TENSOR_MAP_INTERLEAVE_NONE, CU_TENSOR_MAP_SWIZZLE_128B,
      CU_TENSOR_MAP_L2_PROMOTION_L2_128B, CU_TENSOR_MAP_FLOAT_OOB_FILL_NONE);
}
static void enc_3(PFN_tmEnc E, CUtensorMap* m, void* base, uint64_t w, uint64_t h, uint64_t d, uint32_t box1){
    cuuint64_t dims[3] = {w, h, d};
    cuuint64_t strides[2] = {w * 4, w * h * 4};
    cuuint32_t box[3] = {32, box1, 1};
    cuuint32_t es[3] = {1, 1, 1};
    E(m, CU_TENSOR_MAP_DATA_TYPE_FLOAT32, 3, base, dims, strides, box, es,
      CU_TENSOR_MAP_INTERLEAVE_NONE, CU_TENSOR_MAP_SWIZZLE_128B,
      CU_TENSOR_MAP_L2_PROMOTION_L2_128B, CU_TENSOR_MAP_FLOAT_OOB_FILL_NONE);
}

// ---------------- host launcher ----------------
extern "C" void kernel_launch(void* const* d_in, const int* in_sizes, int n_in,
                              void* d_out, int out_size)
{
    const float* x       = (const float*)d_in[0];
    const float* b_in_s  = (const float*)d_in[2];
    const float* att0s   = (const float*)d_in[3];
    const float* alphas  = (const float*)d_in[4];
    const float* b_out_s = (const float*)d_in[6];
    const float* g_out_s = (const float*)d_in[7];
    const float* be_out_s= (const float*)d_in[8];
    const float* b_ff_s  = (const float*)d_in[10];
    const float* g_ff_s  = (const float*)d_in[11];
    const float* be_ff_s = (const float*)d_in[12];
    const float* b_in_t  = (const float*)d_in[14];
    const float* al_f    = (const float*)d_in[15];
    const float* al_b    = (const float*)d_in[16];
    const float* b_out_t = (const float*)d_in[18];
    const float* g_out_t = (const float*)d_in[19];
    const float* be_out_t= (const float*)d_in[20];
    const float* b_ff_t  = (const float*)d_in[22];
    const float* g_ff_t  = (const float*)d_in[23];
    const float* be_ff_t = (const float*)d_in[24];
    const float* b_tcn   = (const float*)d_in[26];
    const float* g_tcn   = (const float*)d_in[27];
    const float* be_tcn  = (const float*)d_in[28];
    float* out = (float*)d_out;

    float *wp, *xT, *qkT, *yT, *s1T, *soT, *sbar, *qtm, *att, *tmaj, *zT, *toT, *tnc;
    cudaGetSymbolAddress((void**)&wp,   g_wp);
    cudaGetSymbolAddress((void**)&xT,   g_xT);
    cudaGetSymbolAddress((void**)&qkT,  g_qkT);
    cudaGetSymbolAddress((void**)&yT,   g_yT);
    cudaGetSymbolAddress((void**)&s1T,  g_s1T);
    cudaGetSymbolAddress((void**)&soT,  g_soT);
    cudaGetSymbolAddress((void**)&sbar, g_sbar);
    cudaGetSymbolAddress((void**)&qtm,  g_qtm);
    cudaGetSymbolAddress((void**)&att,  g_att);
    cudaGetSymbolAddress((void**)&tmaj, g_tmaj);
    cudaGetSymbolAddress((void**)&zT,   g_zT);
    cudaGetSymbolAddress((void**)&toT,  g_toT);
    cudaGetSymbolAddress((void**)&tnc,  g_tnc);

    // build tensormaps via driver entry point (no -lcuda needed)
    static CUtensorMap h_tm[13];
    PFN_tmEnc E = get_enc();
    enc_a(E, &h_tm[0], wp + OFF_WINS,  128, 256);
    enc_a(E, &h_tm[1], wp + OFF_WOUTS, 384, 128);
    enc_a(E, &h_tm[2], wp + OFF_WFFS,  128, 128);
    enc_a(E, &h_tm[3], wp + OFF_WOUTT, 512, 128);
    enc_a(E, &h_tm[4], wp + OFF_WFFT,  128, 128);
    enc_a(E, &h_tm[5], wp + OFF_WTCN,  896, 128);
    enc_3(E, &h_tm[6], att,  128, 128, NB*4, 128);
    enc_3(E, &h_tm[7], xT,   128, TVn, NB, 256);
    enc_3(E, &h_tm[8], yT,   384, TVn, NB, 256);
    enc_3(E, &h_tm[9], s1T,  128, TVn, NB, 256);
    enc_3(E, &h_tm[10], zT,  512, TVn, NB, 256);
    enc_3(E, &h_tm[11], toT, 128, TVn, NB, 256);
    enc_3(E, &h_tm[12], tmaj,128, TVn, NB, 256);
    CUtensorMap* tmd;
    cudaGetSymbolAddress((void**)&tmd, g_tm);
    cudaMemcpyAsync(tmd, h_tm, sizeof(h_tm), cudaMemcpyHostToDevice, 0);

    auto G1w = mma_gemm_w<0,0,0,true,false,false,false,true>;
    auto G2w = mma_gemm_w<0,0,0,true,true,true,true,false>;
    auto G4w = mma_gemm_w<2,0,3,false,false,false,false,false>;
    auto G5w = mma_gemm_w<0,1,1,true,true,true,true,false>;
    auto G3  = mma_gemm<true,false>;
    cudaFuncSetAttribute(G1w, cudaFuncAttributeMaxDynamicSharedMemorySize, SMEMW);
    cudaFuncSetAttribute(G2w, cudaFuncAttributeMaxDynamicSharedMemorySize, SMEMW);
    cudaFuncSetAttribute(G4w, cudaFuncAttributeMaxDynamicSharedMemorySize, SMEMW);
    cudaFuncSetAttribute(G5w, cudaFuncAttributeMaxDynamicSharedMemorySize, SMEMW);
    cudaFuncSetAttribute(G3,  cudaFuncAttributeMaxDynamicSharedMemorySize, SMEMSZ);

    // [0] pack, [1][2] transpose x
    pack_all<<<(W_TOTAL+255)/256,256>>>((const float*)d_in[1], (const float*)d_in[5],
        (const float*)d_in[9], (const float*)d_in[13], (const float*)d_in[17],
        (const float*)d_in[21], (const float*)d_in[25]);
    txpose_x<<<dim3(100,4,16),256>>>(x, 0);
    txpose_x<<<dim3(100,4,16),256>>>(x, 16);

    // qk = W_in_s @ x + b
    G1w<<<dim3(13,2,NB),512,SMEMW>>>(tmd+0, tmd+7, qkT,
        b_in_s, nullptr, nullptr, nullptr, 192, 192, 4, TVn);

    // satt, ymix
    satt_kernel<<<dim3(128,3,NB),256>>>(att0s, alphas);
    ymix_kernel<<<dim3(128,3,NB),128>>>();

    // s1 = lrelu(x + bn(W_out_s @ y + b))  K=384
    G2w<<<dim3(13,1,NB),512,SMEMW>>>(tmd+1, tmd+8, s1T,
        b_out_s, g_out_s, be_out_s, xT, 128, 128, 12, TVn);

    // sout = lrelu(x + bn(W_ff_s @ s1 + b))
    G2w<<<dim3(13,1,NB),512,SMEMW>>>(tmd+2, tmd+9, soT,
        b_ff_s, g_ff_s, be_ff_s, xT, 128, 128, 4, TVn);

    // meanv, qtm (narrow)
    meanv_kernel<<<(NB*128*128+255)/256,256>>>();
    G3<<<dim3(1,2,NB),256,SMEMSZ>>>(wp+OFF_WINT, sbar, qtm,
        b_in_t, 128, 128, 256, 256, 4, 128);

    // tatt
    tatt_kernel<<<NB*16,256>>>(al_f, al_b);

    // sout -> tmaj
    txpose_tmaj<<<dim3(16,25,NB),256>>>();

    // z (temporal mix): per (n,s) M=128 N=3200 K=128
    G4w<<<dim3(13,1,NB*4),512,SMEMW>>>(tmd+6, tmd+12, zT,
        nullptr, nullptr, nullptr, nullptr, 512, 128, 4, TVn);

    // t1 = lrelu(sout + bn(W_out_t @ z + b))  K=512
    G2w<<<dim3(13,1,NB),512,SMEMW>>>(tmd+3, tmd+10, s1T,
        b_out_t, g_out_t, be_out_t, soT, 128, 128, 16, TVn);

    // tout = lrelu(sout + bn(W_ff_t @ t1 + b))
    G2w<<<dim3(13,1,NB),512,SMEMW>>>(tmd+4, tmd+9, toT,
        b_ff_t, g_ff_t, be_ff_t, soT, 128, 128, 4, TVn);

    // toT -> NCHW
    txpose_inv<<<dim3(100,4,NB),256>>>();

    // out = lrelu(tout + bn(tcn7(tout)+b))  K=896 im2col
    G5w<<<dim3(13,1,NB),512,SMEMW>>>(tmd+5, tmd+11, out,
        b_tcn, g_tcn, be_tcn, tnc, 128, 128, 28, TVn);
}